// round 1
// baseline (speedup 1.0000x reference)
#include <cuda_runtime.h>

#define BB   2
#define NC   6
#define CCH  256
#define FHH  28
#define FWW  50
#define HWF  (FHH*FWW)      // 1400
#define PP   40000
#define ZZ   3

// u_norm = u * (fW/IMG_W) / (fW-1) * 2 - 1
__device__ __constant__ float CU2 = (float)((50.0/1600.0)/49.0*2.0);
__device__ __constant__ float CV2 = (float)((28.0/900.0)/27.0*2.0);

// Scratch (zero-initialized device globals; no allocations anywhere)
__device__ float  g_featC[(size_t)BB*NC*HWF*CCH + 64*CCH]; // conv-ed features + OOB pad (stays 0)
__device__ float  g_wt[CCH*CCH];                           // W transposed: wt[c][o]
__device__ int    g_idx[ZZ*NC*BB*PP];                      // corner base index or -1
__device__ float4 g_w[ZZ*NC*BB*PP];                        // 4 bilinear weights
__device__ float  g_invc[ZZ*BB*PP];                        // 1/(count+1e-6)

// ---------------------------------------------------------------------------
// Kernel 1: transpose conv_w (o,c) -> wt (c,o)
// ---------------------------------------------------------------------------
__global__ void transpose_w(const float* __restrict__ w)
{
    int t = blockIdx.x * 256 + threadIdx.x;   // 65536 threads
    int c = t >> 8, o = t & 255;
    g_wt[c*CCH + o] = w[o*CCH + c];
}

// ---------------------------------------------------------------------------
// Kernel 2: per-(b,n) GEMM: featC[hw][o] = sum_c feats[c][hw] * W[o][c]
// BM=128 (hw), BN=64 (o), BK=16, 256 threads, 8x4 micro-tile.
// ---------------------------------------------------------------------------
__global__ __launch_bounds__(256) void conv_gemm(const float* __restrict__ feats)
{
    const int bn = blockIdx.z;
    const int m0 = blockIdx.x * 128;
    const int n0 = blockIdx.y * 64;
    const float* A = feats + (size_t)bn * CCH * HWF;
    float* D = g_featC + (size_t)bn * HWF * CCH;

    __shared__ float As[16][128];
    __shared__ float Bs[16][64];

    const int tid = threadIdx.x;
    const int tm = tid & 15;       // 16 m-groups of 8
    const int tn = tid >> 4;       // 16 n-groups of 4

    float acc[8][4];
#pragma unroll
    for (int i = 0; i < 8; i++)
#pragma unroll
        for (int j = 0; j < 4; j++) acc[i][j] = 0.f;

    for (int k0 = 0; k0 < CCH; k0 += 16) {
#pragma unroll
        for (int pass = 0; pass < 8; pass++) {
            int e = tid + 256 * pass;
            int k = e >> 7, m = e & 127;
            int gm = m0 + m;
            As[k][m] = (gm < HWF) ? A[(size_t)(k0 + k) * HWF + gm] : 0.f;
        }
#pragma unroll
        for (int pass = 0; pass < 4; pass++) {
            int e = tid + 256 * pass;
            int k = e >> 6, nn = e & 63;
            Bs[k][nn] = g_wt[(k0 + k) * CCH + n0 + nn];
        }
        __syncthreads();
#pragma unroll
        for (int kk = 0; kk < 16; kk++) {
            float4 a0 = *(const float4*)&As[kk][tm * 8];
            float4 a1 = *(const float4*)&As[kk][tm * 8 + 4];
            float4 bv = *(const float4*)&Bs[kk][tn * 4];
            float av[8] = {a0.x, a0.y, a0.z, a0.w, a1.x, a1.y, a1.z, a1.w};
            float bw[4] = {bv.x, bv.y, bv.z, bv.w};
#pragma unroll
            for (int i = 0; i < 8; i++)
#pragma unroll
                for (int j = 0; j < 4; j++)
                    acc[i][j] = fmaf(av[i], bw[j], acc[i][j]);
        }
        __syncthreads();
    }

#pragma unroll
    for (int i = 0; i < 8; i++) {
        int m = m0 + tm * 8 + i;
        if (m < HWF) {
            float4 r = make_float4(acc[i][0], acc[i][1], acc[i][2], acc[i][3]);
            *(float4*)&D[(size_t)m * CCH + n0 + tn * 4] = r;
        }
    }
}

// ---------------------------------------------------------------------------
// Kernel 3: projection. One thread per (b,z,p). Writes records in per-(z,n)
// planes so stores are coalesced and sampling reads are warp-uniform.
// ---------------------------------------------------------------------------
__global__ __launch_bounds__(256) void proj_kernel(const float* __restrict__ intr,
                                                   const float* __restrict__ extr,
                                                   const float* __restrict__ pts)
{
    int t = blockIdx.x * blockDim.x + threadIdx.x;
    if (t >= BB * ZZ * PP) return;
    int p  = t % PP;
    int zb = t / PP;
    int z  = zb % ZZ;
    int b  = zb / ZZ;

    const float* q = pts + ((size_t)z * PP + p) * 3;
    float px = q[0], py = q[1], pz = q[2];
    float cnt = 0.f;

#pragma unroll
    for (int n = 0; n < NC; n++) {
        const float* E  = extr + (b * NC + n) * 16;
        const float* Kc = intr + (b * NC + n) * 9;
        // E_inv = [R^T | -R^T t]  (rigid transform)
        float Xc = px*E[0] + py*E[4] + pz*E[8]  - (E[0]*E[3] + E[4]*E[7] + E[8]*E[11]);
        float Yc = px*E[1] + py*E[5] + pz*E[9]  - (E[1]*E[3] + E[5]*E[7] + E[9]*E[11]);
        float Zc = px*E[2] + py*E[6] + pz*E[10] - (E[2]*E[3] + E[6]*E[7] + E[10]*E[11]);
        float fx = Kc[0], cx = Kc[2], fy = Kc[4], cy = Kc[5];
        float inv = 1.f / (Zc + 1e-6f);
        float un = (fx * Xc + cx * Zc) * inv * CU2 - 1.f;
        float vn = (fy * Yc + cy * Zc) * inv * CV2 - 1.f;
        bool valid = (Zc > 0.1f) && (un >= -1.f) && (un <= 1.f) && (vn >= -1.f) && (vn <= 1.f);

        int idx = -1;
        float4 w = make_float4(0.f, 0.f, 0.f, 0.f);
        if (valid) {
            float x = (un + 1.f) * 0.5f * (float)(FWW - 1);
            float y = (vn + 1.f) * 0.5f * (float)(FHH - 1);
            float x0f = floorf(x), y0f = floorf(y);
            float wx1 = x - x0f, wy1 = y - y0f;
            float wx0 = 1.f - wx1, wy0 = 1.f - wy1;
            int x0 = (int)x0f, y0 = (int)y0f;
            w = make_float4(wx0 * wy0, wx1 * wy0, wx0 * wy1, wx1 * wy1);
            if (x0 >= FWW - 1) { w.y = 0.f; w.w = 0.f; }  // x1 out of range, weight 0
            if (y0 >= FHH - 1) { w.z = 0.f; w.w = 0.f; }
            idx = y0 * FWW + x0;
            cnt += 1.f;
        }
        int rp = ((z * NC + n) * BB + b) * PP + p;
        g_idx[rp] = idx;
        g_w[rp]   = w;
    }
    g_invc[(z * BB + b) * PP + p] = 1.f / (cnt + 1e-6f);
}

// ---------------------------------------------------------------------------
// Kernel 4: sampling + BN/ReLU epilogue + coalesced transposed output.
// Block: 256 threads = 4 pixel-lanes x 64 float4-channel-groups. 32 px/block.
// ---------------------------------------------------------------------------
__global__ __launch_bounds__(256) void sample_kernel(const float* __restrict__ convb,
                                                     const float* __restrict__ gamma,
                                                     const float* __restrict__ beta,
                                                     const float* __restrict__ mean,
                                                     const float* __restrict__ var,
                                                     float* __restrict__ out)
{
    __shared__ float so[32 * 257];

    const int b   = blockIdx.y;
    const int p0  = blockIdx.x * 32;
    const int tid = threadIdx.x;
    const int c4  = tid & 63;     // channel quad
    const int ps  = tid >> 6;     // pixel sub-lane 0..3
    const int o0  = c4 * 4;

    // BN + conv bias epilogue constants (per 4 channels)
    float4 cb = *(const float4*)&convb[o0];
    float4 gm = *(const float4*)&gamma[o0];
    float4 bt = *(const float4*)&beta[o0];
    float4 mn = *(const float4*)&mean[o0];
    float4 vr = *(const float4*)&var[o0];
    float4 sc, bi;
    sc.x = gm.x * rsqrtf(vr.x + 1e-5f);  bi.x = (cb.x - mn.x) * sc.x + bt.x;
    sc.y = gm.y * rsqrtf(vr.y + 1e-5f);  bi.y = (cb.y - mn.y) * sc.y + bt.y;
    sc.z = gm.z * rsqrtf(vr.z + 1e-5f);  bi.z = (cb.z - mn.z) * sc.z + bt.z;
    sc.w = gm.w * rsqrtf(vr.w + 1e-5f);  bi.w = (cb.w - mn.w) * sc.w + bt.w;

    const float4* fc = (const float4*)g_featC;
    const float THIRD = 1.f / 3.f;

#pragma unroll 1
    for (int i = 0; i < 8; i++) {
        int p = p0 + ps * 8 + i;
        float4 a = make_float4(0.f, 0.f, 0.f, 0.f);
#pragma unroll
        for (int z = 0; z < ZZ; z++) {
            float4 s = make_float4(0.f, 0.f, 0.f, 0.f);
#pragma unroll
            for (int n = 0; n < NC; n++) {
                int rp = ((z * NC + n) * BB + b) * PP + p;
                int idx = g_idx[rp];                   // warp-uniform
                if (idx >= 0) {
                    float4 w = g_w[rp];
                    const float4* f = fc + ((size_t)(b * NC + n) * HWF + idx) * 64 + c4;
                    float4 v00 = f[0];
                    float4 v01 = f[64];
                    float4 v10 = f[FWW * 64];
                    float4 v11 = f[(FWW + 1) * 64];
                    s.x += w.x*v00.x + w.y*v01.x + w.z*v10.x + w.w*v11.x;
                    s.y += w.x*v00.y + w.y*v01.y + w.z*v10.y + w.w*v11.y;
                    s.z += w.x*v00.z + w.y*v01.z + w.z*v10.z + w.w*v11.z;
                    s.w += w.x*v00.w + w.y*v01.w + w.z*v10.w + w.w*v11.w;
                }
            }
            float ic = g_invc[(z * BB + b) * PP + p];
            a.x += s.x * ic;  a.y += s.y * ic;
            a.z += s.z * ic;  a.w += s.w * ic;
        }
        float4 r;
        r.x = fmaxf(fmaf(a.x * THIRD, sc.x, bi.x), 0.f);
        r.y = fmaxf(fmaf(a.y * THIRD, sc.y, bi.y), 0.f);
        r.z = fmaxf(fmaf(a.z * THIRD, sc.z, bi.z), 0.f);
        r.w = fmaxf(fmaf(a.w * THIRD, sc.w, bi.w), 0.f);
        int row = (ps * 8 + i) * 257 + o0;
        so[row + 0] = r.x;  so[row + 1] = r.y;
        so[row + 2] = r.z;  so[row + 3] = r.w;
    }
    __syncthreads();

    // Transposed write-out: warp writes 32 consecutive pixels of one o-row.
    size_t ob = (size_t)b * CCH * PP + p0;
    int lane = tid & 31;
    int wrp  = tid >> 5;
#pragma unroll
    for (int ot = 0; ot < 32; ot++) {
        int o = wrp + ot * 8;
        out[ob + (size_t)o * PP + lane] = so[lane * 257 + o];
    }
}

// ---------------------------------------------------------------------------
extern "C" void kernel_launch(void* const* d_in, const int* in_sizes, int n_in,
                              void* d_out, int out_size)
{
    const float* feats = (const float*)d_in[0];
    const float* intr  = (const float*)d_in[1];
    const float* extr  = (const float*)d_in[2];
    const float* pts   = (const float*)d_in[3];
    const float* convw = (const float*)d_in[4];
    const float* convb = (const float*)d_in[5];
    const float* gamma = (const float*)d_in[6];
    const float* beta  = (const float*)d_in[7];
    const float* mean  = (const float*)d_in[8];
    const float* var   = (const float*)d_in[9];
    float* out = (float*)d_out;

    transpose_w<<<256, 256>>>(convw);
    conv_gemm<<<dim3(11, 4, BB * NC), 256>>>(feats);
    proj_kernel<<<(BB * ZZ * PP + 255) / 256, 256>>>(intr, extr, pts);
    sample_kernel<<<dim3(PP / 32, BB), 256>>>(convb, gamma, beta, mean, var, out);
}

// round 2
// speedup vs baseline: 1.2965x; 1.2965x over previous
#include <cuda_runtime.h>

#define BB   2
#define NC   6
#define CCH  256
#define FHH  28
#define FWW  50
#define HWF  (FHH*FWW)      // 1400
#define PP   40000
#define ZZ   3
#define NR   (ZZ*NC)        // 18 records per (b,p)

// u_norm = u * (fW/IMG_W) / (fW-1) * 2 - 1
__device__ __constant__ float CU2 = (float)((50.0/1600.0)/49.0*2.0);
__device__ __constant__ float CV2 = (float)((28.0/900.0)/27.0*2.0);

// Scratch (zero-initialized device globals; no allocations anywhere)
__device__ float  g_featC[(size_t)BB*NC*HWF*CCH + 64*CCH]; // conv-ed features + OOB pad (stays 0)
__device__ float  g_wt[CCH*CCH];                           // W transposed: wt[c][o]
__device__ int    g_idx[NR*BB*PP];                         // corner base index or -1
__device__ float4 g_w[NR*BB*PP];                           // 4 bilinear weights (pre-scaled by invc/3)

// ---------------------------------------------------------------------------
// Kernel 1: transpose conv_w (o,c) -> wt (c,o)
// ---------------------------------------------------------------------------
__global__ void transpose_w(const float* __restrict__ w)
{
    int t = blockIdx.x * 256 + threadIdx.x;   // 65536 threads
    int c = t >> 8, o = t & 255;
    g_wt[c*CCH + o] = w[o*CCH + c];
}

// ---------------------------------------------------------------------------
// Kernel 2: per-(b,n) GEMM: featC[hw][o] = sum_c feats[c][hw] * W[o][c]
// BM=128 (hw), BN=64 (o), BK=16, 256 threads, 8x4 micro-tile.
// ---------------------------------------------------------------------------
__global__ __launch_bounds__(256) void conv_gemm(const float* __restrict__ feats)
{
    const int bn = blockIdx.z;
    const int m0 = blockIdx.x * 128;
    const int n0 = blockIdx.y * 64;
    const float* A = feats + (size_t)bn * CCH * HWF;
    float* D = g_featC + (size_t)bn * HWF * CCH;

    __shared__ float As[16][128];
    __shared__ float Bs[16][64];

    const int tid = threadIdx.x;
    const int tm = tid & 15;       // 16 m-groups of 8
    const int tn = tid >> 4;       // 16 n-groups of 4

    float acc[8][4];
#pragma unroll
    for (int i = 0; i < 8; i++)
#pragma unroll
        for (int j = 0; j < 4; j++) acc[i][j] = 0.f;

    for (int k0 = 0; k0 < CCH; k0 += 16) {
#pragma unroll
        for (int pass = 0; pass < 8; pass++) {
            int e = tid + 256 * pass;
            int k = e >> 7, m = e & 127;
            int gm = m0 + m;
            As[k][m] = (gm < HWF) ? A[(size_t)(k0 + k) * HWF + gm] : 0.f;
        }
#pragma unroll
        for (int pass = 0; pass < 4; pass++) {
            int e = tid + 256 * pass;
            int k = e >> 6, nn = e & 63;
            Bs[k][nn] = g_wt[(k0 + k) * CCH + n0 + nn];
        }
        __syncthreads();
#pragma unroll
        for (int kk = 0; kk < 16; kk++) {
            float4 a0 = *(const float4*)&As[kk][tm * 8];
            float4 a1 = *(const float4*)&As[kk][tm * 8 + 4];
            float4 bv = *(const float4*)&Bs[kk][tn * 4];
            float av[8] = {a0.x, a0.y, a0.z, a0.w, a1.x, a1.y, a1.z, a1.w};
            float bw[4] = {bv.x, bv.y, bv.z, bv.w};
#pragma unroll
            for (int i = 0; i < 8; i++)
#pragma unroll
                for (int j = 0; j < 4; j++)
                    acc[i][j] = fmaf(av[i], bw[j], acc[i][j]);
        }
        __syncthreads();
    }

#pragma unroll
    for (int i = 0; i < 8; i++) {
        int m = m0 + tm * 8 + i;
        if (m < HWF) {
            float4 r = make_float4(acc[i][0], acc[i][1], acc[i][2], acc[i][3]);
            *(float4*)&D[(size_t)m * CCH + n0 + tn * 4] = r;
        }
    }
}

// ---------------------------------------------------------------------------
// Kernel 3: projection. One thread per (b,z,p). Buffers the 6 camera records,
// then scales weights by 1/(count+1e-6)/3 so sampling is a flat weighted sum.
// ---------------------------------------------------------------------------
__global__ __launch_bounds__(256) void proj_kernel(const float* __restrict__ intr,
                                                   const float* __restrict__ extr,
                                                   const float* __restrict__ pts)
{
    int t = blockIdx.x * blockDim.x + threadIdx.x;
    if (t >= BB * ZZ * PP) return;
    int p  = t % PP;
    int zb = t / PP;
    int z  = zb % ZZ;
    int b  = zb / ZZ;

    const float* q = pts + ((size_t)z * PP + p) * 3;
    float px = q[0], py = q[1], pz = q[2];
    float cnt = 0.f;

    int    ibuf[NC];
    float4 wbuf[NC];

#pragma unroll
    for (int n = 0; n < NC; n++) {
        const float* E  = extr + (b * NC + n) * 16;
        const float* Kc = intr + (b * NC + n) * 9;
        // E_inv = [R^T | -R^T t]  (rigid transform)
        float Xc = px*E[0] + py*E[4] + pz*E[8]  - (E[0]*E[3] + E[4]*E[7] + E[8]*E[11]);
        float Yc = px*E[1] + py*E[5] + pz*E[9]  - (E[1]*E[3] + E[5]*E[7] + E[9]*E[11]);
        float Zc = px*E[2] + py*E[6] + pz*E[10] - (E[2]*E[3] + E[6]*E[7] + E[10]*E[11]);
        float fx = Kc[0], cx = Kc[2], fy = Kc[4], cy = Kc[5];
        float inv = 1.f / (Zc + 1e-6f);
        float un = (fx * Xc + cx * Zc) * inv * CU2 - 1.f;
        float vn = (fy * Yc + cy * Zc) * inv * CV2 - 1.f;
        bool valid = (Zc > 0.1f) && (un >= -1.f) && (un <= 1.f) && (vn >= -1.f) && (vn <= 1.f);

        int idx = -1;
        float4 w = make_float4(0.f, 0.f, 0.f, 0.f);
        if (valid) {
            float x = (un + 1.f) * 0.5f * (float)(FWW - 1);
            float y = (vn + 1.f) * 0.5f * (float)(FHH - 1);
            float x0f = floorf(x), y0f = floorf(y);
            float wx1 = x - x0f, wy1 = y - y0f;
            float wx0 = 1.f - wx1, wy0 = 1.f - wy1;
            int x0 = (int)x0f, y0 = (int)y0f;
            w = make_float4(wx0 * wy0, wx1 * wy0, wx0 * wy1, wx1 * wy1);
            if (x0 >= FWW - 1) { w.y = 0.f; w.w = 0.f; }  // x1 out of range, weight 0
            if (y0 >= FHH - 1) { w.z = 0.f; w.w = 0.f; }
            idx = y0 * FWW + x0;
            cnt += 1.f;
        }
        ibuf[n] = idx;
        wbuf[n] = w;
    }

    float icc = (1.f / (cnt + 1e-6f)) * (1.f / 3.f);
#pragma unroll
    for (int n = 0; n < NC; n++) {
        int rp = ((z * NC + n) * BB + b) * PP + p;
        float4 w = wbuf[n];
        w.x *= icc; w.y *= icc; w.z *= icc; w.w *= icc;
        g_idx[rp] = ibuf[n];
        g_w[rp]   = w;
    }
}

// ---------------------------------------------------------------------------
// Kernel 4: sampling + BN/ReLU epilogue + coalesced transposed output.
// 256 threads = 4 pixel-lanes x 64 float4-channel-groups. 32 px/block,
// transposed through smem in two 16-pixel chunks (16.4 KB smem).
// Per pixel: all 18 corner indices preloaded first so the 18x(1+4) record
// loads are mutually independent (high MLP), then one flat weighted sum.
// ---------------------------------------------------------------------------
__global__ __launch_bounds__(256, 3) void sample_kernel(const float* __restrict__ convb,
                                                        const float* __restrict__ gamma,
                                                        const float* __restrict__ beta,
                                                        const float* __restrict__ mean,
                                                        const float* __restrict__ var,
                                                        float* __restrict__ out)
{
    __shared__ float so[16 * 257];

    const int b   = blockIdx.y;
    const int p0  = blockIdx.x * 32;
    const int tid = threadIdx.x;
    const int c4  = tid & 63;     // channel quad
    const int ps  = tid >> 6;     // pixel sub-lane 0..3
    const int o0  = c4 * 4;

    // BN + conv bias epilogue constants (per 4 channels)
    float4 cb = *(const float4*)&convb[o0];
    float4 gm = *(const float4*)&gamma[o0];
    float4 bt = *(const float4*)&beta[o0];
    float4 mn = *(const float4*)&mean[o0];
    float4 vr = *(const float4*)&var[o0];
    float4 sc, bi;
    sc.x = gm.x * rsqrtf(vr.x + 1e-5f);  bi.x = (cb.x - mn.x) * sc.x + bt.x;
    sc.y = gm.y * rsqrtf(vr.y + 1e-5f);  bi.y = (cb.y - mn.y) * sc.y + bt.y;
    sc.z = gm.z * rsqrtf(vr.z + 1e-5f);  bi.z = (cb.z - mn.z) * sc.z + bt.z;
    sc.w = gm.w * rsqrtf(vr.w + 1e-5f);  bi.w = (cb.w - mn.w) * sc.w + bt.w;

    const float4* fc = (const float4*)g_featC;
    const size_t  ob = (size_t)b * CCH * PP + p0;

#pragma unroll 1
    for (int chunk = 0; chunk < 2; chunk++) {
#pragma unroll 1
        for (int i = 0; i < 4; i++) {
            const int lp = ps * 4 + i;            // local pixel 0..15
            const int p  = p0 + chunk * 16 + lp;

            // Preload all 18 corner indices (independent, warp-uniform loads)
            int idxs[NR];
#pragma unroll
            for (int r = 0; r < NR; r++)
                idxs[r] = g_idx[(r * BB + b) * PP + p];

            float4 a = make_float4(0.f, 0.f, 0.f, 0.f);
#pragma unroll
            for (int z = 0; z < ZZ; z++) {
#pragma unroll
                for (int n = 0; n < NC; n++) {
                    const int r = z * NC + n;
                    const int idx = idxs[r];
                    if (idx >= 0) {
                        float4 w = g_w[(r * BB + b) * PP + p];
                        const float4* f = fc + ((size_t)(b * NC + n) * HWF + idx) * 64 + c4;
                        float4 v00 = f[0];
                        float4 v01 = f[64];
                        float4 v10 = f[FWW * 64];
                        float4 v11 = f[(FWW + 1) * 64];
                        a.x += w.x*v00.x + w.y*v01.x + w.z*v10.x + w.w*v11.x;
                        a.y += w.x*v00.y + w.y*v01.y + w.z*v10.y + w.w*v11.y;
                        a.z += w.x*v00.z + w.y*v01.z + w.z*v10.z + w.w*v11.z;
                        a.w += w.x*v00.w + w.y*v01.w + w.z*v10.w + w.w*v11.w;
                    }
                }
            }
            float4 rres;
            rres.x = fmaxf(fmaf(a.x, sc.x, bi.x), 0.f);
            rres.y = fmaxf(fmaf(a.y, sc.y, bi.y), 0.f);
            rres.z = fmaxf(fmaf(a.z, sc.z, bi.z), 0.f);
            rres.w = fmaxf(fmaf(a.w, sc.w, bi.w), 0.f);
            int row = lp * 257 + o0;
            so[row + 0] = rres.x;  so[row + 1] = rres.y;
            so[row + 2] = rres.z;  so[row + 3] = rres.w;
        }
        __syncthreads();

        // Transposed write-out: 16 consecutive threads write 16 consecutive
        // pixels of one o-row (64B coalesced stores).
        const int px = tid & 15;
        const int og = tid >> 4;          // 0..15
#pragma unroll
        for (int ot = 0; ot < 16; ot++) {
            int o = og + ot * 16;
            out[ob + (size_t)o * PP + chunk * 16 + px] = so[px * 257 + o];
        }
        __syncthreads();
    }
}

// ---------------------------------------------------------------------------
extern "C" void kernel_launch(void* const* d_in, const int* in_sizes, int n_in,
                              void* d_out, int out_size)
{
    const float* feats = (const float*)d_in[0];
    const float* intr  = (const float*)d_in[1];
    const float* extr  = (const float*)d_in[2];
    const float* pts   = (const float*)d_in[3];
    const float* convw = (const float*)d_in[4];
    const float* convb = (const float*)d_in[5];
    const float* gamma = (const float*)d_in[6];
    const float* beta  = (const float*)d_in[7];
    const float* mean  = (const float*)d_in[8];
    const float* var   = (const float*)d_in[9];
    float* out = (float*)d_out;

    transpose_w<<<256, 256>>>(convw);
    conv_gemm<<<dim3(11, 4, BB * NC), 256>>>(feats);
    proj_kernel<<<(BB * ZZ * PP + 255) / 256, 256>>>(intr, extr, pts);
    sample_kernel<<<dim3(PP / 32, BB), 256>>>(convb, gamma, beta, mean, var, out);
}